// round 12
// baseline (speedup 1.0000x reference)
#include <cuda_runtime.h>
#include <limits.h>

// Problem shape (fixed by setup_inputs): B=256, N=65536, half=32768.
#define NCOL    65536
#define HALF    32768
#define C4ROW   8192              // float4 per half-row
#define QSPLIT  4                 // CTAs per row
#define QC4     (C4ROW / QSPLIT)  // 2048 float4 per quarter (per half)
#define BDIM    512
#define QITER   (QC4 / BDIM)      // 4
#define NROWMAX 512
#define MAXGRID (NROWMAX * QSPLIT)

#define THRESH  0.01f
#define PENALTY 2.0f

// Zero-initialized; all mutable state reset by its last reader each run.
__device__ float    g_cta[MAXGRID];
__device__ float    g_rowcorr[NROWMAX];
__device__ int      g_encf_r[NROWMAX];   // atomicMax of (C4ROW - min_c4); 0 = none
__device__ int      g_encl_r[NROWMAX];   // atomicMax of (max_c4 + 1);     0 = none
__device__ int      g_encf_i[NROWMAX];
__device__ int      g_encl_i[NROWMAX];
__device__ unsigned g_rowcnt[NROWMAX];
__device__ unsigned g_done = 0;

// ---- cache-policy loads (createpolicy + L2::cache_hint form) ---------------
__device__ __forceinline__ unsigned long long mk_keep() {
    unsigned long long pol;
    asm("createpolicy.fractional.L2::evict_last.b64 %0, 1.0;" : "=l"(pol));
    return pol;
}
__device__ __forceinline__ unsigned long long mk_stream() {
    unsigned long long pol;
    asm("createpolicy.fractional.L2::evict_first.b64 %0, 1.0;" : "=l"(pol));
    return pol;
}
__device__ __forceinline__ float4 ld_pol(const float4* p, unsigned long long pol) {
    float4 v;
    asm volatile("ld.global.nc.L2::cache_hint.v4.f32 {%0,%1,%2,%3}, [%4], %5;"
                 : "=f"(v.x), "=f"(v.y), "=f"(v.z), "=f"(v.w)
                 : "l"(p), "l"(pol));
    return v;
}

__global__ __launch_bounds__(BDIM, 2)
void fused_loss_kernel(const float* __restrict__ pred,
                       const float* __restrict__ lab,
                       float* __restrict__ out,
                       int B)
{
    const int u = blockIdx.x;
    const int r = u >> 2;                  // QSPLIT = 4
    const int q = u & 3;
    const size_t row = (size_t)r * NCOL;
    const int qo = q * QC4;                // quarter's base c4 (within half)

    const float4* __restrict__ lr4 = (const float4*)(lab + row);
    const float4* __restrict__ li4 = lr4 + C4ROW;
    const float4* __restrict__ pr4 = (const float4*)(pred + row);
    const float4* __restrict__ pi4 = pr4 + C4ROW;

    const unsigned long long PK = mk_keep();
    const unsigned long long PS = mk_stream();

    const int tid  = threadIdx.x;
    const int lane = tid & 31;
    const int warp = tid >> 5;

    __shared__ int   s_minr, s_maxr, s_mini, s_maxi;
    __shared__ int   s_docorr, s_lastall;
    __shared__ float s_warp[BDIM / 32];

    if (tid == 0) {
        s_minr = INT_MAX; s_maxr = -1;
        s_mini = INT_MAX; s_maxi = -1;
    }
    __syncthreads();

    // ==== Phase 1: scan label quarter (2 contiguous 32KB streams) ============
    int tminr = INT_MAX, tmaxr = -1;
    int tmini = INT_MAX, tmaxi = -1;

    #pragma unroll
    for (int it = 0; it < QITER; it++) {               // real half
        int c4 = qo + tid + it * BDIM;
        float4 v = ld_pol(lr4 + c4, PK);
        float m = fmaxf(fmaxf(fabsf(v.x), fabsf(v.y)), fmaxf(fabsf(v.z), fabsf(v.w)));
        if (m > THRESH) { tminr = min(tminr, c4); tmaxr = max(tmaxr, c4); }
    }
    #pragma unroll
    for (int it = 0; it < QITER; it++) {               // imag half
        int c4 = qo + tid + it * BDIM;
        float4 v = ld_pol(li4 + c4, PK);
        float m = fmaxf(fmaxf(fabsf(v.x), fabsf(v.y)), fmaxf(fabsf(v.z), fabsf(v.w)));
        if (m > THRESH) { tmini = min(tmini, c4); tmaxi = max(tmaxi, c4); }
    }

    #pragma unroll
    for (int off = 16; off > 0; off >>= 1) {
        tminr = min(tminr, __shfl_xor_sync(0xFFFFFFFFu, tminr, off));
        tmaxr = max(tmaxr, __shfl_xor_sync(0xFFFFFFFFu, tmaxr, off));
        tmini = min(tmini, __shfl_xor_sync(0xFFFFFFFFu, tmini, off));
        tmaxi = max(tmaxi, __shfl_xor_sync(0xFFFFFFFFu, tmaxi, off));
    }
    if (lane == 0) {
        atomicMin(&s_minr, tminr);
        atomicMax(&s_maxr, tmaxr);
        atomicMin(&s_mini, tmini);
        atomicMax(&s_maxi, tmaxi);
    }
    __syncthreads();

    // publish quarter's 4-granular bounds; draw row arrival ticket
    if (tid == 0) {
        if (s_maxr >= 0) {
            atomicMax(&g_encf_r[r], C4ROW - s_minr);
            atomicMax(&g_encl_r[r], s_maxr + 1);
        }
        if (s_maxi >= 0) {
            atomicMax(&g_encf_i[r], C4ROW - s_mini);
            atomicMax(&g_encl_i[r], s_maxi + 1);
        }
        __threadfence();
        unsigned tk = atomicAdd(&g_rowcnt[r], 1u);
        s_docorr = (tk == QSPLIT - 1);
    }
    // no syncthreads needed here: phase 2 is independent of the ticket

    // ==== Phase 2: UNWEIGHTED base loss over quarter (no predicates) =========
    // pred from DRAM (stream), label re-read from L2 (kept by phase 1).
    float accR = 0.0f, accI = 0.0f, accQ = 0.0f;

    #pragma unroll 2
    for (int it = 0; it < QITER; it++) {
        int c4 = qo + tid + it * BDIM;
        float4 lrv = ld_pol(lr4 + c4, PS);
        float4 liv = ld_pol(li4 + c4, PS);
        float4 prv = ld_pol(pr4 + c4, PS);
        float4 piv = ld_pol(pi4 + c4, PS);

        #pragma unroll
        for (int k = 0; k < 4; k++) {
            float lrx = (&lrv.x)[k];
            float lix = (&liv.x)[k];
            float prx = (&prv.x)[k];
            float pix = (&piv.x)[k];

            float dr   = prx - lrx;
            float di   = pix - lix;
            float dint = fmaf(pix, pix, prx * prx) - fmaf(lix, lix, lrx * lrx);

            accR = fmaf(dr, dr, accR);
            accI = fmaf(di, di, accI);
            accQ = fmaf(dint, dint, accQ);
        }
    }
    float acc = accR + accI + 50.0f * accQ;

    __syncthreads();   // makes s_docorr visible; phase-2 regs already consumed

    // ==== Correction by the row's last phase-1 arriver (off critical path) ===
    if (s_docorr) {
        __shared__ int s_b[4];
        if (tid == 0) {
            __threadfence();                       // acquire all quarters' REDs
            int efr = g_encf_r[r], elr = g_encl_r[r];
            int efi = g_encf_i[r], eli = g_encl_i[r];
            const float* Lr = lab + row;
            const float* Lj = Lr + HALF;
            int fr = 0, lrr = HALF - 1, fi = 0, lii = HALF - 1;
            if (elr > 0) {                          // element-exact refinement
                fr  = (C4ROW - efr) * 4; while (fabsf(Lr[fr])  <= THRESH) fr++;
                lrr = (elr - 1) * 4 + 3; while (fabsf(Lr[lrr]) <= THRESH) lrr--;
            }
            if (eli > 0) {
                fi  = (C4ROW - efi) * 4; while (fabsf(Lj[fi])  <= THRESH) fi++;
                lii = (eli - 1) * 4 + 3; while (fabsf(Lj[lii]) <= THRESH) lii--;
            }
            s_b[0] = fr; s_b[1] = lrr; s_b[2] = fi; s_b[3] = lii;
            g_encf_r[r] = 0; g_encl_r[r] = 0;      // reset for graph replay
            g_encf_i[r] = 0; g_encl_i[r] = 0;
            g_rowcnt[r] = 0;
        }
        __syncthreads();
        const int fr = s_b[0], lrr = s_b[1], fi = s_b[2], lii = s_b[3];
        const float* Lr = lab  + row;
        const float* Pr = pred + row;
        const float* Lj = Lr + HALF;
        const float* Pj = Pr + HALF;
        float corr = 0.0f;                          // outside region: tiny, L2 hits
        for (int j = tid; j < fr; j += BDIM)             { float d = Pr[j] - Lr[j]; corr = fmaf(d, d, corr); }
        for (int j = lrr + 1 + tid; j < HALF; j += BDIM) { float d = Pr[j] - Lr[j]; corr = fmaf(d, d, corr); }
        for (int j = tid; j < fi; j += BDIM)             { float d = Pj[j] - Lj[j]; corr = fmaf(d, d, corr); }
        for (int j = lii + 1 + tid; j < HALF; j += BDIM) { float d = Pj[j] - Lj[j]; corr = fmaf(d, d, corr); }
        #pragma unroll
        for (int off = 16; off > 0; off >>= 1)
            corr += __shfl_xor_sync(0xFFFFFFFFu, corr, off);
        if (lane == 0) s_warp[warp] = corr;
        __syncthreads();
        if (tid == 0) {
            float cs = 0.0f;
            #pragma unroll
            for (int w = 0; w < BDIM / 32; w++) cs += s_warp[w];
            g_rowcorr[r] = (PENALTY - 1.0f) * cs;   // row-deterministic value
        }
        __syncthreads();
    }

    // ---- CTA fold of base sum ----------------------------------------------
    #pragma unroll
    for (int off = 16; off > 0; off >>= 1)
        acc += __shfl_xor_sync(0xFFFFFFFFu, acc, off);
    if (lane == 0) s_warp[warp] = acc;
    __syncthreads();
    if (tid == 0) {
        float a = 0.0f;
        #pragma unroll
        for (int w = 0; w < BDIM / 32; w++) a += s_warp[w];
        g_cta[u] = a;
        __threadfence();
        unsigned t = atomicAdd(&g_done, 1u);
        s_lastall = (t == (unsigned)(B * QSPLIT - 1));
    }
    __syncthreads();
    if (!s_lastall) return;

    // ---- final fold (fixed order -> deterministic) ---------------------------
    __threadfence();
    __shared__ float s_fin[BDIM];
    float v = 0.0f;
    for (int i = tid; i < B * QSPLIT; i += BDIM) v += g_cta[i];
    for (int i = tid; i < B;          i += BDIM) v += g_rowcorr[i];
    s_fin[tid] = v;
    __syncthreads();
    #pragma unroll
    for (int st = BDIM / 2; st > 0; st >>= 1) {
        if (tid < st) s_fin[tid] += s_fin[tid + st];
        __syncthreads();
    }
    if (tid == 0) {
        out[0] = s_fin[0] / ((float)HALF * (float)B);
        g_done = 0;   // reset for graph replay
    }
}

extern "C" void kernel_launch(void* const* d_in, const int* in_sizes, int n_in,
                              void* d_out, int out_size)
{
    const float* pred = (const float*)d_in[0];
    const float* lab  = (const float*)d_in[1];
    float* out = (float*)d_out;

    const int B = in_sizes[0] / NCOL;   // 256

    fused_loss_kernel<<<B * QSPLIT, BDIM>>>(pred, lab, out, B);
}

// round 13
// speedup vs baseline: 1.2154x; 1.2154x over previous
#include <cuda_runtime.h>
#include <limits.h>

// Problem shape (fixed by setup_inputs): B=256, N=65536, half=32768.
#define NCOL    65536
#define HALF    32768
#define C4ROW   8192              // float4 per half-row
#define C4FULL  16384             // float4 per full row
#define BDIM    512
#define NSM     148
#define GRID    (2 * NSM)         // 296
#define NFULL   NSM               // rows 0..147 -> dedicated full-row CTAs
#define NROWMAX 512

#define THRESH  0.01f
#define PENALTY 2.0f

// Zero-initialized; enc/cnt reset by last reader, done reset by folder,
// rowcorr always rewritten before read -> clean graph replays.
__device__ float    g_cta[GRID];
__device__ float    g_rowcorr[NROWMAX];
__device__ int      g_encf_r[NROWMAX];  // atomicMax of (C4ROW - min_c4); 0 = none
__device__ int      g_encl_r[NROWMAX];  // atomicMax of (max_c4 + 1);     0 = none
__device__ int      g_encf_i[NROWMAX];
__device__ int      g_encl_i[NROWMAX];
__device__ unsigned g_rowcnt[NROWMAX];
__device__ unsigned g_done = 0;

// ---- cache-policy loads (createpolicy + L2::cache_hint form) ---------------
__device__ __forceinline__ unsigned long long mk_keep() {
    unsigned long long pol;
    asm("createpolicy.fractional.L2::evict_last.b64 %0, 1.0;" : "=l"(pol));
    return pol;
}
__device__ __forceinline__ unsigned long long mk_stream() {
    unsigned long long pol;
    asm("createpolicy.fractional.L2::evict_first.b64 %0, 1.0;" : "=l"(pol));
    return pol;
}
__device__ __forceinline__ float4 ld_pol(const float4* p, unsigned long long pol) {
    float4 v;
    asm volatile("ld.global.nc.L2::cache_hint.v4.f32 {%0,%1,%2,%3}, [%4], %5;"
                 : "=f"(v.x), "=f"(v.y), "=f"(v.z), "=f"(v.w)
                 : "l"(p), "l"(pol));
    return v;
}
__device__ __forceinline__ float m4(float4 v) {
    return fmaxf(fmaxf(fabsf(v.x), fabsf(v.y)), fmaxf(fabsf(v.z), fabsf(v.w)));
}

__global__ __launch_bounds__(BDIM, 2)
void fused_loss_kernel(const float* __restrict__ pred,
                       const float* __restrict__ lab,
                       float* __restrict__ out,
                       int B)
{
    const int bid  = blockIdx.x;
    const int tid  = threadIdx.x;
    const int lane = tid & 31;
    const int warp = tid >> 5;

    const unsigned long long PK = mk_keep();
    const unsigned long long PS = mk_stream();

    __shared__ int   s_minr, s_maxr, s_mini, s_maxi;
    __shared__ int   s_b[4];
    __shared__ float s_warp[BDIM / 32];
    __shared__ int   s_doc[2];
    __shared__ int   s_lastall;

    float acc = 0.0f;

    if (bid < NFULL) {
        // =================== FULL-ROW CTA: row = bid, fully local ============
        const int r = bid;
        const size_t row = (size_t)r * NCOL;
        const float4* lr4 = (const float4*)(lab + row);
        const float4* li4 = lr4 + C4ROW;
        const float4* pr4 = (const float4*)(pred + row);
        const float4* pi4 = pr4 + C4ROW;

        if (tid == 0) { s_minr = INT_MAX; s_maxr = -1; s_mini = INT_MAX; s_maxi = -1; }
        __syncthreads();

        // Phase 1: contiguous scan of the 256KB label row (evict_last)
        int tminr = INT_MAX, tmaxr = -1, tmini = INT_MAX, tmaxi = -1;
        #pragma unroll 8
        for (int it = 0; it < 16; it++) {
            int c4 = tid + it * BDIM;
            float4 v = ld_pol(lr4 + c4, PK);
            if (m4(v) > THRESH) { tminr = min(tminr, c4); tmaxr = max(tmaxr, c4); }
        }
        #pragma unroll 8
        for (int it = 0; it < 16; it++) {
            int c4 = tid + it * BDIM;
            float4 v = ld_pol(li4 + c4, PK);
            if (m4(v) > THRESH) { tmini = min(tmini, c4); tmaxi = max(tmaxi, c4); }
        }
        #pragma unroll
        for (int off = 16; off > 0; off >>= 1) {
            tminr = min(tminr, __shfl_xor_sync(0xFFFFFFFFu, tminr, off));
            tmaxr = max(tmaxr, __shfl_xor_sync(0xFFFFFFFFu, tmaxr, off));
            tmini = min(tmini, __shfl_xor_sync(0xFFFFFFFFu, tmini, off));
            tmaxi = max(tmaxi, __shfl_xor_sync(0xFFFFFFFFu, tmaxi, off));
        }
        if (lane == 0) {
            atomicMin(&s_minr, tminr); atomicMax(&s_maxr, tmaxr);
            atomicMin(&s_mini, tmini); atomicMax(&s_maxi, tmaxi);
        }
        __syncthreads();

        if (tid == 0) {   // element-exact refinement (cache hits)
            const float* Lr = lab + row;
            const float* Lj = Lr + HALF;
            int fr = 0, lrr = HALF - 1, fi = 0, lii = HALF - 1;
            if (s_maxr >= 0) {
                fr  = s_minr * 4;     while (fabsf(Lr[fr])  <= THRESH) fr++;
                lrr = s_maxr * 4 + 3; while (fabsf(Lr[lrr]) <= THRESH) lrr--;
            }
            if (s_maxi >= 0) {
                fi  = s_mini * 4;     while (fabsf(Lj[fi])  <= THRESH) fi++;
                lii = s_maxi * 4 + 3; while (fabsf(Lj[lii]) <= THRESH) lii--;
            }
            s_b[0] = fr; s_b[1] = lrr; s_b[2] = fi; s_b[3] = lii;
        }
        __syncthreads();

        // Phase 2: UNWEIGHTED base loss (no predicates, no index math)
        float aR = 0.0f, aI = 0.0f, aQ = 0.0f;
        #pragma unroll 2
        for (int it = 0; it < 16; it++) {
            int c4 = tid + it * BDIM;
            float4 L  = ld_pol(lr4 + c4, PS);
            float4 Li = ld_pol(li4 + c4, PS);
            float4 P  = ld_pol(pr4 + c4, PS);
            float4 Pi = ld_pol(pi4 + c4, PS);
            #pragma unroll
            for (int k = 0; k < 4; k++) {
                float lrx = (&L.x)[k],  lix = (&Li.x)[k];
                float prx = (&P.x)[k],  pix = (&Pi.x)[k];
                float dr = prx - lrx, di = pix - lix;
                float dint = fmaf(pix, pix, prx * prx) - fmaf(lix, lix, lrx * lrx);
                aR = fmaf(dr, dr, aR);
                aI = fmaf(di, di, aI);
                aQ = fmaf(dint, dint, aQ);
            }
        }
        acc = aR + aI + 50.0f * aQ;

        // Local correction (tiny outside region, L2/L1 hits)
        {
            const int fr = s_b[0], lrr = s_b[1], fi = s_b[2], lii = s_b[3];
            const float* Lr = lab  + row;
            const float* Pr = pred + row;
            const float* Lj = Lr + HALF;
            const float* Pj = Pr + HALF;
            float corr = 0.0f;
            for (int j = tid; j < fr; j += BDIM)             { float d = Pr[j] - Lr[j]; corr = fmaf(d, d, corr); }
            for (int j = lrr + 1 + tid; j < HALF; j += BDIM) { float d = Pr[j] - Lr[j]; corr = fmaf(d, d, corr); }
            for (int j = tid; j < fi; j += BDIM)             { float d = Pj[j] - Lj[j]; corr = fmaf(d, d, corr); }
            for (int j = lii + 1 + tid; j < HALF; j += BDIM) { float d = Pj[j] - Lj[j]; corr = fmaf(d, d, corr); }
            acc = fmaf(PENALTY - 1.0f, corr, acc);
        }
    } else {
        // =========== PARTIAL CTA: flat slice of the tail-row pair space ======
        const int p    = bid - NFULL;            // 0..147
        const int TAIL = B - NFULL;              // 108
        const long long TOTP = (long long)TAIL * C4ROW;
        const int y0 = (int)((long long)p       * TOTP / NSM);
        const int y1 = (int)((long long)(p + 1) * TOTP / NSM);
        const int rt0 = y0 / C4ROW;
        const int rt1 = (y1 - 1) / C4ROW;

        // ---- Phase 1: per touched row, scan label slice, publish bounds ----
        for (int t = rt0; t <= rt1; t++) {
            const int a = max(y0 - t * C4ROW, 0);
            const int e = min(y1 - t * C4ROW, C4ROW);
            const size_t row = (size_t)(NFULL + t) * NCOL;
            const float4* lr4 = (const float4*)(lab + row);
            const float4* li4 = lr4 + C4ROW;

            if (tid == 0) { s_minr = INT_MAX; s_maxr = -1; s_mini = INT_MAX; s_maxi = -1; }
            __syncthreads();

            int tminr = INT_MAX, tmaxr = -1, tmini = INT_MAX, tmaxi = -1;
            #pragma unroll 4
            for (int j = a + tid; j < e; j += BDIM) {
                float4 v = ld_pol(lr4 + j, PK);
                if (m4(v) > THRESH) { tminr = min(tminr, j); tmaxr = max(tmaxr, j); }
            }
            #pragma unroll 4
            for (int j = a + tid; j < e; j += BDIM) {
                float4 v = ld_pol(li4 + j, PK);
                if (m4(v) > THRESH) { tmini = min(tmini, j); tmaxi = max(tmaxi, j); }
            }
            #pragma unroll
            for (int off = 16; off > 0; off >>= 1) {
                tminr = min(tminr, __shfl_xor_sync(0xFFFFFFFFu, tminr, off));
                tmaxr = max(tmaxr, __shfl_xor_sync(0xFFFFFFFFu, tmaxr, off));
                tmini = min(tmini, __shfl_xor_sync(0xFFFFFFFFu, tmini, off));
                tmaxi = max(tmaxi, __shfl_xor_sync(0xFFFFFFFFu, tmaxi, off));
            }
            if (lane == 0) {
                atomicMin(&s_minr, tminr); atomicMax(&s_maxr, tmaxr);
                atomicMin(&s_mini, tmini); atomicMax(&s_maxi, tmaxi);
            }
            __syncthreads();

            if (tid == 0) {
                const int gr = NFULL + t;
                if (s_maxr >= 0) {
                    atomicMax(&g_encf_r[gr], C4ROW - s_minr);
                    atomicMax(&g_encl_r[gr], s_maxr + 1);
                }
                if (s_maxi >= 0) {
                    atomicMax(&g_encf_i[gr], C4ROW - s_mini);
                    atomicMax(&g_encl_i[gr], s_maxi + 1);
                }
                __threadfence();
                long long lo = (long long)t * C4ROW, hi = lo + C4ROW;
                int cf = (int)(((lo + 1) * NSM + TOTP - 1) / TOTP) - 1;
                int cl = (int)((hi * NSM + TOTP - 1) / TOTP) - 1;
                unsigned tk = atomicAdd(&g_rowcnt[gr], 1u);
                s_doc[t - rt0] = (tk == (unsigned)(cl - cf));
            }
            __syncthreads();
        }

        // ---- Phase 2: unweighted base loss over the slice ------------------
        float aR = 0.0f, aI = 0.0f, aQ = 0.0f;
        for (int t = rt0; t <= rt1; t++) {
            const int a = max(y0 - t * C4ROW, 0);
            const int e = min(y1 - t * C4ROW, C4ROW);
            const size_t row = (size_t)(NFULL + t) * NCOL;
            const float4* lr4 = (const float4*)(lab + row);
            const float4* li4 = lr4 + C4ROW;
            const float4* pr4 = (const float4*)(pred + row);
            const float4* pi4 = pr4 + C4ROW;

            #pragma unroll 2
            for (int j = a + tid; j < e; j += BDIM) {
                float4 L  = ld_pol(lr4 + j, PS);
                float4 Li = ld_pol(li4 + j, PS);
                float4 P  = ld_pol(pr4 + j, PS);
                float4 Pi = ld_pol(pi4 + j, PS);
                #pragma unroll
                for (int k = 0; k < 4; k++) {
                    float lrx = (&L.x)[k],  lix = (&Li.x)[k];
                    float prx = (&P.x)[k],  pix = (&Pi.x)[k];
                    float dr = prx - lrx, di = pix - lix;
                    float dint = fmaf(pix, pix, prx * prx) - fmaf(lix, lix, lrx * lrx);
                    aR = fmaf(dr, dr, aR);
                    aI = fmaf(di, di, aI);
                    aQ = fmaf(dint, dint, aQ);
                }
            }
        }
        acc = aR + aI + 50.0f * aQ;

        // ---- Row corrections by last arriver (off critical path) -----------
        __syncthreads();
        for (int t = rt0; t <= rt1; t++) {
            if (!s_doc[t - rt0]) continue;
            const int gr = NFULL + t;
            const size_t row = (size_t)gr * NCOL;
            if (tid == 0) {
                __threadfence();
                int efr = g_encf_r[gr], elr = g_encl_r[gr];
                int efi = g_encf_i[gr], eli = g_encl_i[gr];
                const float* Lr = lab + row;
                const float* Lj = Lr + HALF;
                int fr = 0, lrr = HALF - 1, fi = 0, lii = HALF - 1;
                if (elr > 0) {
                    fr  = (C4ROW - efr) * 4; while (fabsf(Lr[fr])  <= THRESH) fr++;
                    lrr = (elr - 1) * 4 + 3; while (fabsf(Lr[lrr]) <= THRESH) lrr--;
                }
                if (eli > 0) {
                    fi  = (C4ROW - efi) * 4; while (fabsf(Lj[fi])  <= THRESH) fi++;
                    lii = (eli - 1) * 4 + 3; while (fabsf(Lj[lii]) <= THRESH) lii--;
                }
                s_b[0] = fr; s_b[1] = lrr; s_b[2] = fi; s_b[3] = lii;
                g_encf_r[gr] = 0; g_encl_r[gr] = 0;
                g_encf_i[gr] = 0; g_encl_i[gr] = 0;
                g_rowcnt[gr] = 0;
            }
            __syncthreads();
            const int fr = s_b[0], lrr = s_b[1], fi = s_b[2], lii = s_b[3];
            const float* Lr = lab  + row;
            const float* Pr = pred + row;
            const float* Lj = Lr + HALF;
            const float* Pj = Pr + HALF;
            float corr = 0.0f;
            for (int j = tid; j < fr; j += BDIM)             { float d = Pr[j] - Lr[j]; corr = fmaf(d, d, corr); }
            for (int j = lrr + 1 + tid; j < HALF; j += BDIM) { float d = Pr[j] - Lr[j]; corr = fmaf(d, d, corr); }
            for (int j = tid; j < fi; j += BDIM)             { float d = Pj[j] - Lj[j]; corr = fmaf(d, d, corr); }
            for (int j = lii + 1 + tid; j < HALF; j += BDIM) { float d = Pj[j] - Lj[j]; corr = fmaf(d, d, corr); }
            #pragma unroll
            for (int off = 16; off > 0; off >>= 1)
                corr += __shfl_xor_sync(0xFFFFFFFFu, corr, off);
            if (lane == 0) s_warp[warp] = corr;
            __syncthreads();
            if (tid == 0) {
                float cs = 0.0f;
                #pragma unroll
                for (int w = 0; w < BDIM / 32; w++) cs += s_warp[w];
                g_rowcorr[gr] = (PENALTY - 1.0f) * cs;   // row-deterministic
            }
            __syncthreads();
        }
    }

    // ==================== common epilogue: fold + ticket =====================
    #pragma unroll
    for (int off = 16; off > 0; off >>= 1)
        acc += __shfl_xor_sync(0xFFFFFFFFu, acc, off);
    if (lane == 0) s_warp[warp] = acc;
    __syncthreads();
    if (tid == 0) {
        float a = 0.0f;
        #pragma unroll
        for (int w = 0; w < BDIM / 32; w++) a += s_warp[w];
        g_cta[bid] = a;
        __threadfence();
        unsigned t = atomicAdd(&g_done, 1u);
        s_lastall = (t == (unsigned)(GRID - 1));
    }
    __syncthreads();
    if (!s_lastall) return;

    // ---- final fold (fixed order -> deterministic) ---------------------------
    __threadfence();
    __shared__ float s_fin[BDIM];
    float v = 0.0f;
    for (int i = tid; i < GRID; i += BDIM) v += g_cta[i];
    for (int i = NFULL + tid; i < B; i += BDIM) v += g_rowcorr[i];
    s_fin[tid] = v;
    __syncthreads();
    #pragma unroll
    for (int st = BDIM / 2; st > 0; st >>= 1) {
        if (tid < st) s_fin[tid] += s_fin[tid + st];
        __syncthreads();
    }
    if (tid == 0) {
        out[0] = s_fin[0] / ((float)HALF * (float)B);
        g_done = 0;   // reset for graph replay
    }
}

extern "C" void kernel_launch(void* const* d_in, const int* in_sizes, int n_in,
                              void* d_out, int out_size)
{
    const float* pred = (const float*)d_in[0];
    const float* lab  = (const float*)d_in[1];
    float* out = (float*)d_out;

    const int B = in_sizes[0] / NCOL;   // 256

    fused_loss_kernel<<<GRID, BDIM>>>(pred, lab, out, B);
}

// round 14
// speedup vs baseline: 1.4143x; 1.1636x over previous
#include <cuda_runtime.h>
#include <limits.h>

// Problem shape (fixed by setup_inputs): B=256, N=65536, half=32768.
#define NCOL   65536
#define HALF   32768
#define C4ROW  8192              // float4 per half-row
#define BDIM   512
#define MAXB   1024

#define THRESH  0.01f
#define PENALTY 2.0f

__device__ float        g_partials[MAXB];
__device__ unsigned int g_counter = 0;

// ---- cache-policy loads (createpolicy + L2::cache_hint form) ---------------
__device__ __forceinline__ unsigned long long mk_policy_evict_last() {
    unsigned long long pol;
    asm("createpolicy.fractional.L2::evict_last.b64 %0, 1.0;" : "=l"(pol));
    return pol;
}
__device__ __forceinline__ unsigned long long mk_policy_evict_first() {
    unsigned long long pol;
    asm("createpolicy.fractional.L2::evict_first.b64 %0, 1.0;" : "=l"(pol));
    return pol;
}
__device__ __forceinline__ float4 ld_pol(const float4* p, unsigned long long pol) {
    float4 v;
    asm volatile("ld.global.nc.L2::cache_hint.v4.f32 {%0,%1,%2,%3}, [%4], %5;"
                 : "=f"(v.x), "=f"(v.y), "=f"(v.z), "=f"(v.w)
                 : "l"(p), "l"(pol));
    return v;
}

__global__ __launch_bounds__(BDIM, 2)
void fused_loss_kernel(const float* __restrict__ pred,
                       const float* __restrict__ lab,
                       float* __restrict__ out,
                       int B)
{
    const int b = blockIdx.x;
    const size_t row = (size_t)b * NCOL;
    const float4* __restrict__ lr4 = (const float4*)(lab + row);
    const float4* __restrict__ li4 = lr4 + C4ROW;
    const float4* __restrict__ pr4 = (const float4*)(pred + row);
    const float4* __restrict__ pi4 = (const float4*)(pred + row) + C4ROW;

    const unsigned long long pol_keep   = mk_policy_evict_last();
    const unsigned long long pol_stream = mk_policy_evict_first();

    __shared__ int  s_min_r, s_max_r, s_min_i, s_max_i;
    __shared__ int  s_b[4];
    __shared__ bool s_is_last;
    if (threadIdx.x == 0) {
        s_min_r = INT_MAX; s_max_r = -1;
        s_min_i = INT_MAX; s_max_i = -1;
    }
    __syncthreads();

    const int lane = threadIdx.x & 31;
    const int warp = threadIdx.x >> 5;

    // ==== Phase 1: ONE contiguous stream over the full 256KB label row =======
    int tmin_r = INT_MAX, tmax_r = -1;
    int tmin_i = INT_MAX, tmax_i = -1;

    #pragma unroll 8
    for (int it = 0; it < 16; it++) {                    // real half
        int c4 = threadIdx.x + it * BDIM;
        float4 v = ld_pol(lr4 + c4, pol_keep);
        float m = fmaxf(fmaxf(fabsf(v.x), fabsf(v.y)), fmaxf(fabsf(v.z), fabsf(v.w)));
        if (m > THRESH) { tmin_r = min(tmin_r, c4); tmax_r = max(tmax_r, c4); }
    }
    #pragma unroll 8
    for (int it = 0; it < 16; it++) {                    // imag half
        int c4 = threadIdx.x + it * BDIM;
        float4 v = ld_pol(li4 + c4, pol_keep);
        float m = fmaxf(fmaxf(fabsf(v.x), fabsf(v.y)), fmaxf(fabsf(v.z), fabsf(v.w)));
        if (m > THRESH) { tmin_i = min(tmin_i, c4); tmax_i = max(tmax_i, c4); }
    }

    #pragma unroll
    for (int off = 16; off > 0; off >>= 1) {
        tmin_r = min(tmin_r, __shfl_xor_sync(0xFFFFFFFFu, tmin_r, off));
        tmax_r = max(tmax_r, __shfl_xor_sync(0xFFFFFFFFu, tmax_r, off));
        tmin_i = min(tmin_i, __shfl_xor_sync(0xFFFFFFFFu, tmin_i, off));
        tmax_i = max(tmax_i, __shfl_xor_sync(0xFFFFFFFFu, tmax_i, off));
    }
    if (lane == 0) {
        atomicMin(&s_min_r, tmin_r);
        atomicMax(&s_max_r, tmax_r);
        atomicMin(&s_min_i, tmin_i);
        atomicMax(&s_max_i, tmax_i);
    }
    __syncthreads();

    // refine 4-granular bounds to element-exact (matches reference semantics)
    if (threadIdx.x == 0) {
        const float* Lr = lab + row;
        const float* Lj = lab + row + HALF;
        int fr = 0, lrr = HALF - 1, fi = 0, lii = HALF - 1;
        if (s_max_r >= 0) {
            int f = s_min_r * 4;     while (fabsf(Lr[f]) <= THRESH) f++;
            int l = s_max_r * 4 + 3; while (fabsf(Lr[l]) <= THRESH) l--;
            fr = f; lrr = l;
        }
        if (s_max_i >= 0) {
            int f = s_min_i * 4;     while (fabsf(Lj[f]) <= THRESH) f++;
            int l = s_max_i * 4 + 3; while (fabsf(Lj[l]) <= THRESH) l--;
            fi = f; lii = l;
        }
        s_b[0] = fr; s_b[1] = lrr; s_b[2] = fi; s_b[3] = lii;
    }
    __syncthreads();

    // ==== Phase 2: UNWEIGHTED loss; pred from DRAM, label from L2 ============
    // No weight predicates, no per-element index math: pure load + FMA chains.
    float accR = 0.0f, accI = 0.0f, accQ = 0.0f;

    #pragma unroll 2
    for (int it = 0; it < 16; it++) {
        int c4 = threadIdx.x + it * BDIM;
        float4 lrv = ld_pol(lr4 + c4, pol_stream);
        float4 liv = ld_pol(li4 + c4, pol_stream);
        float4 prv = ld_pol(pr4 + c4, pol_stream);
        float4 piv = ld_pol(pi4 + c4, pol_stream);

        #pragma unroll
        for (int k = 0; k < 4; k++) {
            float lrx = (&lrv.x)[k];
            float lix = (&liv.x)[k];
            float prx = (&prv.x)[k];
            float pix = (&piv.x)[k];

            float dr   = prx - lrx;
            float di   = pix - lix;
            float dint = fmaf(pix, pix, prx * prx) - fmaf(lix, lix, lrx * lrx);

            accR = fmaf(dr, dr, accR);
            accI = fmaf(di, di, accI);
            accQ = fmaf(dint, dint, accQ);
        }
    }
    float acc = accR + accI + 50.0f * accQ;

    // ==== Correction: (P-1) * sum of d^2 outside [first,last] ================
    // Outside region is typically ~2 elements per half (N(0,1) labels); reads
    // hit L1/L2. Exact for any input.
    {
        const int fr = s_b[0], lrr = s_b[1], fi = s_b[2], lii = s_b[3];
        const float* Lr = lab  + row;
        const float* Pr = pred + row;
        const float* Lj = Lr + HALF;
        const float* Pj = Pr + HALF;
        float corr = 0.0f;
        for (int j = threadIdx.x; j < fr; j += BDIM)             { float d = Pr[j] - Lr[j]; corr = fmaf(d, d, corr); }
        for (int j = lrr + 1 + threadIdx.x; j < HALF; j += BDIM) { float d = Pr[j] - Lr[j]; corr = fmaf(d, d, corr); }
        for (int j = threadIdx.x; j < fi; j += BDIM)             { float d = Pj[j] - Lj[j]; corr = fmaf(d, d, corr); }
        for (int j = lii + 1 + threadIdx.x; j < HALF; j += BDIM) { float d = Pj[j] - Lj[j]; corr = fmaf(d, d, corr); }
        acc = fmaf(PENALTY - 1.0f, corr, acc);
    }

    // ---- block sum reduction -------------------------------------------------
    __shared__ float s_warp[BDIM / 32];
    #pragma unroll
    for (int off = 16; off > 0; off >>= 1)
        acc += __shfl_xor_sync(0xFFFFFFFFu, acc, off);
    if (lane == 0)
        s_warp[warp] = acc;
    __syncthreads();
    if (threadIdx.x < 32) {
        float v = (threadIdx.x < BDIM / 32) ? s_warp[threadIdx.x] : 0.0f;
        #pragma unroll
        for (int off = 16; off > 0; off >>= 1)
            v += __shfl_xor_sync(0xFFFFFFFFu, v, off);
        if (threadIdx.x == 0)
            g_partials[b] = v;
    }

    // ---- last CTA folds the per-row partials (self-resetting for graphs) ----
    if (threadIdx.x == 0) {
        __threadfence();
        unsigned int ticket = atomicAdd(&g_counter, 1u);
        s_is_last = (ticket == (unsigned int)(B - 1));
    }
    __syncthreads();

    if (s_is_last) {
        __threadfence();
        __shared__ float s_fin[256];
        if (threadIdx.x < 256)
            s_fin[threadIdx.x] = (threadIdx.x < B) ? g_partials[threadIdx.x] : 0.0f;
        __syncthreads();
        #pragma unroll
        for (int st = 128; st > 0; st >>= 1) {
            if (threadIdx.x < st) s_fin[threadIdx.x] += s_fin[threadIdx.x + st];
            __syncthreads();
        }
        if (threadIdx.x == 0) {
            out[0] = s_fin[0] / ((float)HALF * (float)B);
            g_counter = 0;   // reset for graph replay
        }
    }
}

extern "C" void kernel_launch(void* const* d_in, const int* in_sizes, int n_in,
                              void* d_out, int out_size)
{
    const float* pred = (const float*)d_in[0];
    const float* lab  = (const float*)d_in[1];
    float* out = (float*)d_out;

    const int B = in_sizes[0] / NCOL;   // 256

    fused_loss_kernel<<<B, BDIM>>>(pred, lab, out, B);
}

// round 15
// speedup vs baseline: 1.4816x; 1.0476x over previous
#include <cuda_runtime.h>
#include <limits.h>

// Problem shape (fixed by setup_inputs): B=256, N=65536, half=32768.
#define NCOL   65536
#define HALF   32768
#define C8ROW  4096              // float8 per half-row
#define BDIM   512
#define NIT8   (C8ROW / BDIM)    // 8 iterations per half
#define MAXB   1024

#define THRESH  0.01f
#define PENALTY 2.0f

__device__ float        g_partials[MAXB];
__device__ unsigned int g_counter = 0;

struct f8 { float v[8]; };

// 256-bit loads with direct L2 evict hints (the sm_100-legal form).
__device__ __forceinline__ f8 ld8_keep(const float* p) {
    unsigned a0,a1,a2,a3,a4,a5,a6,a7;
    asm volatile("ld.global.nc.L2::evict_last.v8.b32 {%0,%1,%2,%3,%4,%5,%6,%7}, [%8];"
                 : "=r"(a0),"=r"(a1),"=r"(a2),"=r"(a3),
                   "=r"(a4),"=r"(a5),"=r"(a6),"=r"(a7)
                 : "l"(p));
    f8 r;
    r.v[0]=__uint_as_float(a0); r.v[1]=__uint_as_float(a1);
    r.v[2]=__uint_as_float(a2); r.v[3]=__uint_as_float(a3);
    r.v[4]=__uint_as_float(a4); r.v[5]=__uint_as_float(a5);
    r.v[6]=__uint_as_float(a6); r.v[7]=__uint_as_float(a7);
    return r;
}
__device__ __forceinline__ f8 ld8_stream(const float* p) {
    unsigned a0,a1,a2,a3,a4,a5,a6,a7;
    asm volatile("ld.global.nc.L2::evict_first.v8.b32 {%0,%1,%2,%3,%4,%5,%6,%7}, [%8];"
                 : "=r"(a0),"=r"(a1),"=r"(a2),"=r"(a3),
                   "=r"(a4),"=r"(a5),"=r"(a6),"=r"(a7)
                 : "l"(p));
    f8 r;
    r.v[0]=__uint_as_float(a0); r.v[1]=__uint_as_float(a1);
    r.v[2]=__uint_as_float(a2); r.v[3]=__uint_as_float(a3);
    r.v[4]=__uint_as_float(a4); r.v[5]=__uint_as_float(a5);
    r.v[6]=__uint_as_float(a6); r.v[7]=__uint_as_float(a7);
    return r;
}
__device__ __forceinline__ float m8(const f8& x) {
    float a = fmaxf(fabsf(x.v[0]), fabsf(x.v[1]));
    float b = fmaxf(fabsf(x.v[2]), fabsf(x.v[3]));
    float c = fmaxf(fabsf(x.v[4]), fabsf(x.v[5]));
    float d = fmaxf(fabsf(x.v[6]), fabsf(x.v[7]));
    return fmaxf(fmaxf(a, b), fmaxf(c, d));
}

__global__ __launch_bounds__(BDIM, 2)
void fused_loss_kernel(const float* __restrict__ pred,
                       const float* __restrict__ lab,
                       float* __restrict__ out,
                       int B)
{
    const int b = blockIdx.x;
    const size_t row = (size_t)b * NCOL;
    const float* Lr = lab  + row;
    const float* Lj = Lr + HALF;
    const float* Pr = pred + row;
    const float* Pj = Pr + HALF;

    __shared__ int  s_min_r, s_max_r, s_min_i, s_max_i;
    __shared__ int  s_b[4];
    __shared__ bool s_is_last;
    if (threadIdx.x == 0) {
        s_min_r = INT_MAX; s_max_r = -1;
        s_min_i = INT_MAX; s_max_i = -1;
    }
    __syncthreads();

    const int lane = threadIdx.x & 31;
    const int warp = threadIdx.x >> 5;

    // ==== Phase 1: contiguous scan of 256KB label row, 8-granular bounds =====
    int tmin_r = INT_MAX, tmax_r = -1;
    int tmin_i = INT_MAX, tmax_i = -1;

    #pragma unroll 4
    for (int it = 0; it < NIT8; it++) {                  // real half
        int c8 = threadIdx.x + it * BDIM;
        f8 v = ld8_keep(Lr + (size_t)c8 * 8);
        if (m8(v) > THRESH) { tmin_r = min(tmin_r, c8); tmax_r = max(tmax_r, c8); }
    }
    #pragma unroll 4
    for (int it = 0; it < NIT8; it++) {                  // imag half
        int c8 = threadIdx.x + it * BDIM;
        f8 v = ld8_keep(Lj + (size_t)c8 * 8);
        if (m8(v) > THRESH) { tmin_i = min(tmin_i, c8); tmax_i = max(tmax_i, c8); }
    }

    #pragma unroll
    for (int off = 16; off > 0; off >>= 1) {
        tmin_r = min(tmin_r, __shfl_xor_sync(0xFFFFFFFFu, tmin_r, off));
        tmax_r = max(tmax_r, __shfl_xor_sync(0xFFFFFFFFu, tmax_r, off));
        tmin_i = min(tmin_i, __shfl_xor_sync(0xFFFFFFFFu, tmin_i, off));
        tmax_i = max(tmax_i, __shfl_xor_sync(0xFFFFFFFFu, tmax_i, off));
    }
    if (lane == 0) {
        atomicMin(&s_min_r, tmin_r);
        atomicMax(&s_max_r, tmax_r);
        atomicMin(&s_min_i, tmin_i);
        atomicMax(&s_max_i, tmax_i);
    }
    __syncthreads();

    // refine 8-granular bounds to element-exact (cache hits, <=7 steps each)
    if (threadIdx.x == 0) {
        int fr = 0, lrr = HALF - 1, fi = 0, lii = HALF - 1;
        if (s_max_r >= 0) {
            int f = s_min_r * 8;     while (fabsf(Lr[f]) <= THRESH) f++;
            int l = s_max_r * 8 + 7; while (fabsf(Lr[l]) <= THRESH) l--;
            fr = f; lrr = l;
        }
        if (s_max_i >= 0) {
            int f = s_min_i * 8;     while (fabsf(Lj[f]) <= THRESH) f++;
            int l = s_max_i * 8 + 7; while (fabsf(Lj[l]) <= THRESH) l--;
            fi = f; lii = l;
        }
        s_b[0] = fr; s_b[1] = lrr; s_b[2] = fi; s_b[3] = lii;
    }
    __syncthreads();

    // ==== Phase 2: UNWEIGHTED loss; pred from DRAM, label from L2 ============
    // 4 x 256-bit loads per iter (32 data regs in flight), 3 FMA chains.
    float accR = 0.0f, accI = 0.0f, accQ = 0.0f;

    for (int it = 0; it < NIT8; it++) {
        size_t e = (size_t)(threadIdx.x + it * BDIM) * 8;
        f8 L  = ld8_stream(Lr + e);
        f8 Li = ld8_stream(Lj + e);
        f8 P  = ld8_stream(Pr + e);
        f8 Pi = ld8_stream(Pj + e);

        #pragma unroll
        for (int k = 0; k < 8; k++) {
            float lrx = L.v[k],  lix = Li.v[k];
            float prx = P.v[k],  pix = Pi.v[k];

            float dr   = prx - lrx;
            float di   = pix - lix;
            float dint = fmaf(pix, pix, prx * prx) - fmaf(lix, lix, lrx * lrx);

            accR = fmaf(dr, dr, accR);
            accI = fmaf(di, di, accI);
            accQ = fmaf(dint, dint, accQ);
        }
    }
    float acc = accR + accI + 50.0f * accQ;

    // ==== Correction: (P-1) * sum of d^2 outside [first,last] (tiny) =========
    {
        const int fr = s_b[0], lrr = s_b[1], fi = s_b[2], lii = s_b[3];
        float corr = 0.0f;
        for (int j = threadIdx.x; j < fr; j += BDIM)             { float d = Pr[j] - Lr[j]; corr = fmaf(d, d, corr); }
        for (int j = lrr + 1 + threadIdx.x; j < HALF; j += BDIM) { float d = Pr[j] - Lr[j]; corr = fmaf(d, d, corr); }
        for (int j = threadIdx.x; j < fi; j += BDIM)             { float d = Pj[j] - Lj[j]; corr = fmaf(d, d, corr); }
        for (int j = lii + 1 + threadIdx.x; j < HALF; j += BDIM) { float d = Pj[j] - Lj[j]; corr = fmaf(d, d, corr); }
        acc = fmaf(PENALTY - 1.0f, corr, acc);
    }

    // ---- block sum reduction -------------------------------------------------
    __shared__ float s_warp[BDIM / 32];
    #pragma unroll
    for (int off = 16; off > 0; off >>= 1)
        acc += __shfl_xor_sync(0xFFFFFFFFu, acc, off);
    if (lane == 0)
        s_warp[warp] = acc;
    __syncthreads();
    if (threadIdx.x < 32) {
        float v = (threadIdx.x < BDIM / 32) ? s_warp[threadIdx.x] : 0.0f;
        #pragma unroll
        for (int off = 16; off > 0; off >>= 1)
            v += __shfl_xor_sync(0xFFFFFFFFu, v, off);
        if (threadIdx.x == 0)
            g_partials[b] = v;
    }

    // ---- last CTA folds the per-row partials (self-resetting for graphs) ----
    if (threadIdx.x == 0) {
        __threadfence();
        unsigned int ticket = atomicAdd(&g_counter, 1u);
        s_is_last = (ticket == (unsigned int)(B - 1));
    }
    __syncthreads();

    if (s_is_last) {
        __threadfence();
        __shared__ float s_fin[256];
        if (threadIdx.x < 256)
            s_fin[threadIdx.x] = (threadIdx.x < B) ? g_partials[threadIdx.x] : 0.0f;
        __syncthreads();
        #pragma unroll
        for (int st = 128; st > 0; st >>= 1) {
            if (threadIdx.x < st) s_fin[threadIdx.x] += s_fin[threadIdx.x + st];
            __syncthreads();
        }
        if (threadIdx.x == 0) {
            out[0] = s_fin[0] / ((float)HALF * (float)B);
            g_counter = 0;   // reset for graph replay
        }
    }
}

extern "C" void kernel_launch(void* const* d_in, const int* in_sizes, int n_in,
                              void* d_out, int out_size)
{
    const float* pred = (const float*)d_in[0];
    const float* lab  = (const float*)d_in[1];
    float* out = (float*)d_out;

    const int B = in_sizes[0] / NCOL;   // 256

    fused_loss_kernel<<<B, BDIM>>>(pred, lab, out, B);
}